// round 6
// baseline (speedup 1.0000x reference)
#include <cuda_runtime.h>

// Problem constants
// x: (1, 8, 12,12,12, 8, 40) f32 ; weight: (8,8,3,3,3,7) ; bias: (8,3,3,3)
// basis: (12,7,3,3) ; I,J: (8,40) i32 ; T: (12,8,40) i32 ; bias_basis: (96) i32
// out: (1, 96, 12,12,12, 8, 40) f32
//
// Factorization:
//   Y[n,o,b,h,w]   = sum_{c,fi,fj,fk} weight[o,c,fi,fj,fk,b] * x[c, xo+fi, yo+fj, zo+fk, h, w]
//   acc[n,g,o,p,q] = sum_{b,u,v} basis[g,b,u,v] * Y[n,o,b,p+u,q+v]     (p<6, q<38)
//   out[g*8+o, xo+1,yo+1,zo+1, h, w] = acc[n, T[g,h,w]*8+o, I[h,w]-1, J[h,w]-1] + biasSum[o]
//   everything else in out = 0

#define N_BLK   729          // 9*9*9 spatial outputs
#define OB      56           // O(8) * Kb(7)
#define HW      320          // 8*40
#define YTILE   (OB * HW)    // 17920 floats per n

// 52.25 MB scratch for Y  (static __device__ global — allocation-free)
__device__ float Yg[N_BLK * YTILE];

// ---------------------------------------------------------------------------
// Stage 1: Y = weight (*) x      — one block per n, 320 threads
// thread t: og = t/80 selects 14 of the 56 (o,b) outputs; (t%80)*4 = w-quad
// ---------------------------------------------------------------------------
__global__ __launch_bounds__(320, 2)
void stage1(const float* __restrict__ x, const float* __restrict__ w)
{
    __shared__ __align__(16) float Wsm[216 * 56];   // Wsm[(c*27+f)*56 + o*7 + b]

    const int tid = threadIdx.x;
    for (int idx = tid; idx < 12096; idx += 320) {
        int o = idx / 1512;  int r = idx - o * 1512;   // weight idx = o*1512 + c*189 + f*7 + b
        int c = r / 189;     r -= c * 189;
        int f = r / 7;       int b = r - f * 7;
        Wsm[(c * 27 + f) * 56 + o * 7 + b] = w[idx];
    }
    __syncthreads();

    const int n  = blockIdx.x;
    const int xo = n / 81, yo = (n / 9) % 9, zo = n % 9;
    const int og  = tid / 80;            // 0..3  -> outputs [og*14, og*14+14)
    const int hwb = (tid % 80) * 4;      // 4 consecutive w within one h row (40%4==0)

    // x strides (floats): c:552960  xi:46080  yi:3840  zi:320
    const float* xb = x + xo * 46080 + yo * 3840 + zo * 320 + hwb;

    float acc[14][4];
#pragma unroll
    for (int j = 0; j < 14; j++) { acc[j][0]=0.f; acc[j][1]=0.f; acc[j][2]=0.f; acc[j][3]=0.f; }

    for (int c = 0; c < 8; c++) {
        const float* xc = xb  + c * 552960;
        const float* wc = Wsm + c * 27 * 56 + og * 14;
        for (int fi = 0; fi < 3; fi++) {
#pragma unroll
            for (int fj = 0; fj < 3; fj++) {
#pragma unroll
                for (int fk = 0; fk < 3; fk++) {
                    const float4 xv = *reinterpret_cast<const float4*>(
                        xc + fi * 46080 + fj * 3840 + fk * 320);
                    const float* wk = wc + ((fi * 3 + fj) * 3 + fk) * 56;
#pragma unroll
                    for (int j2 = 0; j2 < 7; j2++) {
                        const float2 wj = *reinterpret_cast<const float2*>(wk + 2 * j2);
                        acc[2*j2  ][0] += wj.x * xv.x;  acc[2*j2  ][1] += wj.x * xv.y;
                        acc[2*j2  ][2] += wj.x * xv.z;  acc[2*j2  ][3] += wj.x * xv.w;
                        acc[2*j2+1][0] += wj.y * xv.x;  acc[2*j2+1][1] += wj.y * xv.y;
                        acc[2*j2+1][2] += wj.y * xv.z;  acc[2*j2+1][3] += wj.y * xv.w;
                    }
                }
            }
        }
    }

    float* yptr = Yg + (size_t)n * YTILE + (og * 14) * 320 + hwb;
#pragma unroll
    for (int j = 0; j < 14; j++)
        *reinterpret_cast<float4*>(yptr + j * 320) =
            make_float4(acc[j][0], acc[j][1], acc[j][2], acc[j][3]);
}

// ---------------------------------------------------------------------------
// Stage 2: basis conv + (T,I,J) gather + bias + interior write — 1 block per n
// Phase A: 576 threads, task = (g,o,p), each computes acc[q] for q=0..37
// Phase B: gather to out channels, coalesced over w
// smem: Ys[17920] | accS[21888] | Bs[756] | bias_s[8] | bb_s[96 int]
// ---------------------------------------------------------------------------
__global__ __launch_bounds__(576, 1)
void stage2(const float* __restrict__ basis, const float* __restrict__ bias,
            const int* __restrict__ Tg, const int* __restrict__ Ig,
            const int* __restrict__ Jg, const int* __restrict__ bbg,
            float* __restrict__ out)
{
    extern __shared__ __align__(16) float sm[];
    float* Ys     = sm;                    // 17920 : Ys[(o*7+b)*320 + h*40 + w]
    float* accS   = Ys + YTILE;            // 21888 : accS[((g*8+o)*6+p)*38 + q]
    float* Bs     = accS + 21888;          // 756
    float* bias_s = Bs + 756;              // 8
    int*   bb_s   = (int*)(bias_s + 8);    // 96

    const int tid = threadIdx.x;
    const int n   = blockIdx.x;

    {   // load this n's Y tile (17920 f32 = 4480 float4) into smem
        const float4* src = reinterpret_cast<const float4*>(Yg + (size_t)n * YTILE);
        float4*       dst = reinterpret_cast<float4*>(Ys);
        for (int i = tid; i < YTILE / 4; i += 576) dst[i] = src[i];
    }
    for (int i = tid; i < 756; i += 576) Bs[i] = basis[i];
    if (tid < 96) bb_s[tid] = bbg[tid];
    if (tid < 8) {
        float s = 0.f;
        for (int k = 0; k < 27; k++) s += bias[tid * 27 + k];
        bias_s[tid] = s;
    }
    __syncthreads();

    // ---- Phase A ----
    {
        const int g = tid / 48;          // 12
        const int o = (tid / 6) % 8;     // 8
        const int p = tid % 6;           // 6    (tid == (g*8+o)*6+p)
        float acc[38];
#pragma unroll
        for (int q = 0; q < 38; q++) acc[q] = 0.f;

        for (int b = 0; b < 7; b++) {
#pragma unroll
            for (int u = 0; u < 3; u++) {
                const float* yrow = Ys + (o * 7 + b) * 320 + (p + u) * 40;
                float r[40];
#pragma unroll
                for (int i = 0; i < 10; i++) {
                    const float4 v = reinterpret_cast<const float4*>(yrow)[i];
                    r[4*i] = v.x; r[4*i+1] = v.y; r[4*i+2] = v.z; r[4*i+3] = v.w;
                }
                const float* bp = Bs + ((g * 7 + b) * 3 + u) * 3;
                const float s0 = bp[0], s1 = bp[1], s2 = bp[2];
#pragma unroll
                for (int q = 0; q < 38; q++)
                    acc[q] += s0 * r[q] + s1 * r[q + 1] + s2 * r[q + 2];
            }
        }
        float* ad = accS + tid * 38;
#pragma unroll
        for (int q = 0; q < 38; q++) ad[q] = acc[q];
    }
    __syncthreads();

    // ---- Phase B: gather + write interior of out ----
    const int xo = n / 81, yo = (n / 9) % 9, zo = n % 9;
    float* ob = out + ((xo + 1) * 144 + (yo + 1) * 12 + (zo + 1)) * 320;
    for (int idx = tid; idx < 30720; idx += 576) {
        const int go = idx / 320;
        const int hw = idx - go * 320;
        const int g  = go >> 3, o = go & 7;
        const int t  = Tg[g * 320 + hw];
        const int p  = Ig[hw] - 1;     // in [0,5]
        const int q  = Jg[hw] - 1;     // in [0,37]
        const float v = accS[((t * 8 + o) * 6 + p) * 38 + q] + bias_s[bb_s[t * 8 + o]];
        ob[(size_t)go * 552960 + hw] = v;   // out go-stride = 12*12*12*320
    }
}

// ---------------------------------------------------------------------------
extern "C" void kernel_launch(void* const* d_in, const int* in_sizes, int n_in,
                              void* d_out, int out_size)
{
    const float* x      = (const float*)d_in[0];
    const float* weight = (const float*)d_in[1];
    const float* bias   = (const float*)d_in[2];
    const float* basis  = (const float*)d_in[3];
    const int*   Ig     = (const int*)d_in[4];
    const int*   Jg     = (const int*)d_in[5];
    const int*   Tg     = (const int*)d_in[6];
    const int*   bbg    = (const int*)d_in[7];
    float*       out    = (float*)d_out;

    // zero the whole output (x/y/z boundary voxels stay zero)
    cudaMemsetAsync(d_out, 0, (size_t)out_size * sizeof(float), 0);

    stage1<<<729, 320>>>(x, weight);

    const size_t smem2 = (size_t)(YTILE + 21888 + 756 + 8) * sizeof(float)
                       + 96 * sizeof(int);                       // 162,672 B
    // unconditional every call: idempotent, rule-compliant (no static guards)
    cudaFuncSetAttribute(stage2, cudaFuncAttributeMaxDynamicSharedMemorySize,
                         (int)smem2);
    stage2<<<729, 576, smem2>>>(basis, bias, Tg, Ig, Jg, bbg, out);
}

// round 10
// speedup vs baseline: 1.2603x; 1.2603x over previous
#include <cuda_runtime.h>

// x: (1,8,12,12,12,8,40) f32 ; weight: (8,8,3,3,3,7) ; bias: (8,3,3,3)
// basis: (12,7,3,3) ; I,J: (8,40) i32 ; T: (12,8,40) i32 ; bias_basis: (96) i32
// out: (1,96,12,12,12,8,40) f32
//
// Fused per-voxel kernel (grid = 1728):
//  boundary voxel  -> zero its 96x320 slice
//  interior voxel  -> part1: Y[ob,h,w] = sum_{c,f} weight[o,c,f,b]*x[c,vox+f,h,w]  (smem, padded)
//                     part2: acc[g,o,p,q] = sum_{b,u,v} basis[g,b,u,v]*Y[o*7+b,p+u,q+v]
//                     gather: out[g*8+o,vox,h,w] = acc[T[g,h,w]*8... ,I-1,J-1] + biasSum

#define F_WSM   12096          // 216*56
#define YROW    44             // padded row (40 used)
#define YOBS    356            // per-(o,b) stride: 8*44+4 ; 356/4=89 == 1 mod 8 -> conflict-free
#define F_YS    (56*YOBS)      // 19936
#define F_ACCS  21888          // 96*6*38
#define F_BS    756

#define FMA2(acc, a, b) asm("fma.rn.f32x2 %0, %1, %2, %0;" : "+l"(acc) : "l"(a), "l"(b))
#define PACK2(dst, f)   asm("mov.b64 %0, {%1, %1};" : "=l"(dst) : "r"(__float_as_uint(f)))

__global__ __launch_bounds__(576, 1)
void fused(const float* __restrict__ x, const float* __restrict__ w,
           const float* __restrict__ basis, const float* __restrict__ bias,
           const int* __restrict__ Tg, const int* __restrict__ Ig,
           const int* __restrict__ Jg, const int* __restrict__ bbg,
           float* __restrict__ out)
{
    const int vox = blockIdx.x;
    const int vx = vox / 144, vy = (vox / 12) % 12, vz = vox % 12;
    const int tid = threadIdx.x;

    // ---- boundary voxel: zero the 96 x 320 slice ----
    if (vx < 1 || vx > 9 || vy < 1 || vy > 9 || vz < 1 || vz > 9) {
        const float4 z4 = make_float4(0.f, 0.f, 0.f, 0.f);
        float* ob = out + (size_t)vox * 320;
        for (int i = tid; i < 7680; i += 576) {
            const int ch = i / 80, off = (i % 80) * 4;
            *reinterpret_cast<float4*>(ob + (size_t)ch * 552960 + off) = z4;
        }
        return;
    }

    extern __shared__ __align__(16) float sm[];
    float* Wsm    = sm;                 // Wsm[(c*27+f)*56 + o*7 + b]
    float* Ys     = sm + F_WSM;         // Ys[ob*356 + h*44 + w]
    float* accS   = Ys + F_YS;          // accS[((g*8+o)*6+p)*38 + q]
    float* Bs     = accS + F_ACCS;      // basis copy
    float* bias_s = Bs + F_BS;          // 8 sums
    int*   bb_s   = (int*)(bias_s + 8); // 96

    // ---- cooperative preamble ----
    for (int idx = tid; idx < 12096; idx += 576) {
        int o = idx / 1512;  int r = idx - o * 1512;   // weight idx = o*1512 + c*189 + f*7 + b
        int c = r / 189;     r -= c * 189;
        int f = r / 7;       int b = r - f * 7;
        Wsm[(c * 27 + f) * 56 + o * 7 + b] = w[idx];
    }
    for (int i = tid; i < F_BS; i += 576) Bs[i] = basis[i];
    if (tid < 96) bb_s[tid] = bbg[tid];
    if (tid < 8) {
        float s = 0.f;
        for (int k = 0; k < 27; k++) s += bias[tid * 27 + k];
        bias_s[tid] = s;
    }
    __syncthreads();

    const int xo = vx - 1, yo = vy - 1, zo = vz - 1;

    // ---- part 1: Y = weight (*) x  (560 active threads, 8 outputs x 4 w each) ----
    if (tid < 560) {
        const int og  = tid / 80;            // 0..6 -> outputs [og*8, og*8+8)
        const int hwb = (tid % 80) * 4;
        // x strides (floats): c:552960  xi:46080  yi:3840  zi:320
        const float* xb = x + xo * 46080 + yo * 3840 + zo * 320 + hwb;

        unsigned long long a64[4][4];        // [out pair j][x elem k]
#pragma unroll
        for (int j = 0; j < 4; j++)
#pragma unroll
            for (int k = 0; k < 4; k++) a64[j][k] = 0ull;

        for (int c = 0; c < 8; c++) {
            const float* xc = xb + c * 552960;
            for (int fi = 0; fi < 3; fi++) {
                const float* xcf = xc + fi * 46080;
                const float* wcf = Wsm + (c * 27 + fi * 9) * 56 + og * 8;
#pragma unroll
                for (int f9 = 0; f9 < 9; f9++) {
                    const int fj = f9 / 3, fk = f9 % 3;
                    const float4 xv = *reinterpret_cast<const float4*>(
                        xcf + fj * 3840 + fk * 320);
                    unsigned long long xq0, xq1, xq2, xq3;
                    PACK2(xq0, xv.x); PACK2(xq1, xv.y);
                    PACK2(xq2, xv.z); PACK2(xq3, xv.w);
                    const unsigned long long* wq =
                        reinterpret_cast<const unsigned long long*>(wcf + f9 * 56);
#pragma unroll
                    for (int j = 0; j < 4; j++) {
                        const unsigned long long wv = wq[j];
                        FMA2(a64[j][0], wv, xq0);
                        FMA2(a64[j][1], wv, xq1);
                        FMA2(a64[j][2], wv, xq2);
                        FMA2(a64[j][3], wv, xq3);
                    }
                }
            }
        }

        const int h = hwb / 40, w0 = hwb % 40;
#pragma unroll
        for (int j = 0; j < 4; j++) {
            float r0[4], r1[4];
#pragma unroll
            for (int k = 0; k < 4; k++) {
                unsigned lo, hi;
                asm("mov.b64 {%0, %1}, %2;" : "=r"(lo), "=r"(hi) : "l"(a64[j][k]));
                r0[k] = __uint_as_float(lo);
                r1[k] = __uint_as_float(hi);
            }
            float* p0 = Ys + (og * 8 + 2 * j) * YOBS + h * YROW + w0;
            *reinterpret_cast<float4*>(p0)        = make_float4(r0[0], r0[1], r0[2], r0[3]);
            *reinterpret_cast<float4*>(p0 + YOBS) = make_float4(r1[0], r1[1], r1[2], r1[3]);
        }
    }
    __syncthreads();

    // ---- part 2: basis conv, thread = (g,o,p), tid == (g*8+o)*6+p ----
    {
        const int g = tid / 48;
        const int o = (tid / 6) % 8;
        const int p = tid % 6;
        float acc[38];
#pragma unroll
        for (int q = 0; q < 38; q++) acc[q] = 0.f;

        for (int b = 0; b < 7; b++) {
#pragma unroll
            for (int u = 0; u < 3; u++) {
                const float* yrow = Ys + (o * 7 + b) * YOBS + (p + u) * YROW;
                float r[40];
#pragma unroll
                for (int i = 0; i < 10; i++) {
                    const float4 v = reinterpret_cast<const float4*>(yrow)[i];
                    r[4*i] = v.x; r[4*i+1] = v.y; r[4*i+2] = v.z; r[4*i+3] = v.w;
                }
                const float* bp = Bs + ((g * 7 + b) * 3 + u) * 3;
                const float s0 = bp[0], s1 = bp[1], s2 = bp[2];
#pragma unroll
                for (int q = 0; q < 38; q++)
                    acc[q] += s0 * r[q] + s1 * r[q + 1] + s2 * r[q + 2];
            }
        }
        float* ad = accS + tid * 38;
#pragma unroll
        for (int q = 0; q < 38; q++) ad[q] = acc[q];
    }
    __syncthreads();

    // ---- gather + write interior slice ----
    float* ob = out + (size_t)vox * 320;
    for (int idx = tid; idx < 30720; idx += 576) {
        const int go = idx / 320;
        const int hw = idx - go * 320;
        const int g  = go >> 3, o = go & 7;
        const int t  = Tg[g * 320 + hw];
        const int p  = Ig[hw] - 1;     // [0,5]
        const int q  = Jg[hw] - 1;     // [0,37]
        const float v = accS[((t * 8 + o) * 6 + p) * 38 + q] + bias_s[bb_s[t * 8 + o]];
        ob[(size_t)go * 552960 + hw] = v;
    }
}

// ---------------------------------------------------------------------------
extern "C" void kernel_launch(void* const* d_in, const int* in_sizes, int n_in,
                              void* d_out, int out_size)
{
    const float* x      = (const float*)d_in[0];
    const float* weight = (const float*)d_in[1];
    const float* bias   = (const float*)d_in[2];
    const float* basis  = (const float*)d_in[3];
    const int*   Ig     = (const int*)d_in[4];
    const int*   Jg     = (const int*)d_in[5];
    const int*   Tg     = (const int*)d_in[6];
    const int*   bbg    = (const int*)d_in[7];
    float*       out    = (float*)d_out;

    const size_t smem = (size_t)(F_WSM + F_YS + F_ACCS + F_BS + 8) * sizeof(float)
                      + 96 * sizeof(int);                       // 219,120 B
    cudaFuncSetAttribute(fused, cudaFuncAttributeMaxDynamicSharedMemorySize, (int)smem);
    fused<<<1728, 576, smem>>>(x, weight, basis, bias, Tg, Ig, Jg, bbg, out);
}